// round 5
// baseline (speedup 1.0000x reference)
#include <cuda_runtime.h>

// RPE MHA, sm_100a. B=2, N=M=512, C=256, H=8, D=32.
// scores_p computed as embed . wq (wq = Wp-projected q), avoiding the
// (B*N*M,C)x(C,C) projection of embed.

#define SCALE_Q 0.17677669529663687f  // 32^-0.5, folded into q projection

__device__ float g_q[1024 * 256];
__device__ float g_k[1024 * 256];
__device__ float g_v[1024 * 256];
__device__ float g_wq[8 * 1024 * 256];     // [h][bn][c]
__device__ float g_se[16 * 512 * 512];     // [b*8+h][n][m]
__device__ float g_attn[16 * 512 * 512];   // [b*8+h][n][m]
__device__ float g_hid[1024 * 256];        // [bn][c]

// 64xN tiled fp32 GEMM, 256 threads, K-tile 16.
// BT=false: C = A[m][k] @ B[k][n].  BT=true: C = A[m][k] @ B[n][k].
template <bool BT, int TN>
__device__ __forceinline__ void gemm_body(
    const float* __restrict__ A, int lda,
    const float* __restrict__ B, int ldb,
    float* __restrict__ C, int ldc,
    int N, int K, float scale, const float* __restrict__ bias)
{
    __shared__ float As[64][20];
    __shared__ float Bs[16][68];

    const int tid = threadIdx.x;
    const int m0 = blockIdx.x * 64;
    const int n0 = blockIdx.y * 64;
    const int lr = tid >> 2;
    const int lc = (tid & 3) << 2;

    constexpr int RM = (TN == 64) ? 4 : 2;
    const int ty = (TN == 64) ? (tid >> 4) : (tid >> 3);
    const int tx = (TN == 64) ? (tid & 15) : (tid & 7);

    float acc[RM][4];
#pragma unroll
    for (int i = 0; i < RM; i++)
#pragma unroll
        for (int j = 0; j < 4; j++) acc[i][j] = 0.0f;

    for (int k0 = 0; k0 < K; k0 += 16) {
        float4 a4 = *(const float4*)(A + (long)(m0 + lr) * lda + k0 + lc);
        *(float4*)&As[lr][lc] = a4;
        if (BT) {
            float4 b4 = *(const float4*)(B + (long)(n0 + lr) * ldb + k0 + lc);
            Bs[lc + 0][lr] = b4.x;
            Bs[lc + 1][lr] = b4.y;
            Bs[lc + 2][lr] = b4.z;
            Bs[lc + 3][lr] = b4.w;
        } else {
            const int bk = tid >> 4;
            const int bn = (tid & 15) << 2;
            float4 b4 = make_float4(0.f, 0.f, 0.f, 0.f);
            if (n0 + bn < N)
                b4 = *(const float4*)(B + (long)(k0 + bk) * ldb + n0 + bn);
            *(float4*)&Bs[bk][bn] = b4;
        }
        __syncthreads();

#pragma unroll
        for (int kk = 0; kk < 16; kk++) {
            float a[RM];
#pragma unroll
            for (int i = 0; i < RM; i++) a[i] = As[ty * RM + i][kk];
            float4 bb = *(const float4*)&Bs[kk][tx * 4];
#pragma unroll
            for (int i = 0; i < RM; i++) {
                acc[i][0] += a[i] * bb.x;
                acc[i][1] += a[i] * bb.y;
                acc[i][2] += a[i] * bb.z;
                acc[i][3] += a[i] * bb.w;
            }
        }
        __syncthreads();
    }

#pragma unroll
    for (int i = 0; i < RM; i++) {
#pragma unroll
        for (int j = 0; j < 4; j++) {
            int n = n0 + tx * 4 + j;
            if (n < N) {
                float v = acc[i][j] * scale;
                if (bias) v += bias[n];
                C[(long)(m0 + ty * RM + i) * ldc + n] = v;
            }
        }
    }
}

__device__ __forceinline__ long zoff(int z, long o1, long o2)
{
    return (long)(z >> 3) * o1 + (long)(z & 7) * o2;
}

__global__ void __launch_bounds__(256) k_gemm_nt(
    const float* A, int lda, long oA1, long oA2,
    const float* B, int ldb, long oB1, long oB2,
    float* C, int ldc, long oC1, long oC2,
    int N, int K, float scale)
{
    int z = blockIdx.z;
    gemm_body<true, 64>(A + zoff(z, oA1, oA2), lda,
                        B + zoff(z, oB1, oB2), ldb,
                        C + zoff(z, oC1, oC2), ldc, N, K, scale, nullptr);
}

__global__ void __launch_bounds__(256) k_gemm_nn64(
    const float* A, int lda, long oA1, long oA2,
    const float* B, int ldb, long oB1, long oB2,
    float* C, int ldc, long oC1, long oC2,
    int N, int K, float scale, const float* bias)
{
    int z = blockIdx.z;
    gemm_body<false, 64>(A + zoff(z, oA1, oA2), lda,
                         B + zoff(z, oB1, oB2), ldb,
                         C + zoff(z, oC1, oC2), ldc, N, K, scale, bias);
}

__global__ void __launch_bounds__(256) k_gemm_nn32(
    const float* A, int lda, long oA1, long oA2,
    const float* B, int ldb, long oB1, long oB2,
    float* C, int ldc, long oC1, long oC2,
    int N, int K, float scale)
{
    int z = blockIdx.z;
    gemm_body<false, 32>(A + zoff(z, oA1, oA2), lda,
                         B + zoff(z, oB1, oB2), ldb,
                         C + zoff(z, oC1, oC2), ldc, N, K, scale, nullptr);
}

__global__ void __launch_bounds__(256) k_gemm_qkv(
    const float* Aq, const float* Ak, const float* Av,
    const float* Bq, const float* Bk, const float* Bv,
    float* Cq, float* Ck, float* Cv)
{
    int z = blockIdx.z;
    const float* A = (z == 0) ? Aq : (z == 1) ? Ak : Av;
    const float* B = (z == 0) ? Bq : (z == 1) ? Bk : Bv;
    float*       C = (z == 0) ? Cq : (z == 1) ? Ck : Cv;
    gemm_body<false, 64>(A, 256, B, 256, C, 256, 256, 256,
                         (z == 0) ? SCALE_Q : 1.0f, nullptr);
}

// Fused scores_p + add scores_e + softmax -> attn.
// CTA per (b,n), 256 threads. Thread t owns m=t and m=t+256 for all 8 heads.
#define FK_AS_FLOATS (2 * 512 * 17)
#define FK_SMEM_BYTES ((FK_AS_FLOATS + 256 * 8 + 8 * 512) * 4)

__global__ void __launch_bounds__(256) k_fused_score_softmax(
    const float* __restrict__ embed,  // [b][n][m][c]
    const float* __restrict__ wq,     // [h][bn][c]
    const float* __restrict__ se,     // [b*8+h][n][m]
    float* __restrict__ attn)         // [b*8+h][n][m]
{
    extern __shared__ float sm[];
    float* As  = sm;                   // [2][512][17]
    float* BsW = sm + FK_AS_FLOATS;    // [c][h]
    float* S   = BsW + 256 * 8;        // [h][m]

    const int n = blockIdx.x;
    const int b = blockIdx.y;
    const int t = threadIdx.x;
    const long bn = (long)b * 512 + n;
    const float* Ebase = embed + bn * (512L * 256);

#pragma unroll
    for (int h = 0; h < 8; h++)
        BsW[t * 8 + h] = wq[((long)h * 1024 + bn) * 256 + t];

    float acc0[8], acc1[8];
#pragma unroll
    for (int h = 0; h < 8; h++) { acc0[h] = 0.f; acc1[h] = 0.f; }

    const int mb = t >> 2;
    const int ch = t & 3;
    const float* gp0 = Ebase + (long)mb * 256 + ch * 4;

    float4 stage[8];
#define FK_LOAD(kt)                                                     \
    {                                                                   \
        const float* gp = gp0 + (kt) * 16;                              \
        _Pragma("unroll")                                               \
        for (int j = 0; j < 8; j++)                                     \
            stage[j] = *(const float4*)(gp + (long)j * 64 * 256);       \
    }
#define FK_STS(buf)                                                     \
    {                                                                   \
        float* dst = As + (buf) * (512 * 17) + ch * 4;                  \
        _Pragma("unroll")                                               \
        for (int j = 0; j < 8; j++) {                                   \
            float* p = dst + (j * 64 + mb) * 17;                        \
            p[0] = stage[j].x; p[1] = stage[j].y;                       \
            p[2] = stage[j].z; p[3] = stage[j].w;                       \
        }                                                               \
    }

    FK_LOAD(0);
    FK_STS(0);
    __syncthreads();

    int cur = 0;
    for (int kt = 0; kt < 16; kt++) {
        if (kt < 15) FK_LOAD(kt + 1);

        const float* Ar0 = As + cur * (512 * 17) + t * 17;
        const float* Ar1 = Ar0 + 256 * 17;
        const float* bw  = BsW + kt * 16 * 8;
#pragma unroll
        for (int kk = 0; kk < 16; kk++) {
            float a0 = Ar0[kk];
            float a1 = Ar1[kk];
            float4 bA = *(const float4*)(bw + kk * 8);
            float4 bB = *(const float4*)(bw + kk * 8 + 4);
            acc0[0] += a0 * bA.x;  acc0[1] += a0 * bA.y;
            acc0[2] += a0 * bA.z;  acc0[3] += a0 * bA.w;
            acc0[4] += a0 * bB.x;  acc0[5] += a0 * bB.y;
            acc0[6] += a0 * bB.z;  acc0[7] += a0 * bB.w;
            acc1[0] += a1 * bA.x;  acc1[1] += a1 * bA.y;
            acc1[2] += a1 * bA.z;  acc1[3] += a1 * bA.w;
            acc1[4] += a1 * bB.x;  acc1[5] += a1 * bB.y;
            acc1[6] += a1 * bB.z;  acc1[7] += a1 * bB.w;
        }
        if (kt < 15) FK_STS(cur ^ 1);
        __syncthreads();
        cur ^= 1;
    }

    const float* seb = se + (long)(b * 8) * 262144 + (long)n * 512;
#pragma unroll
    for (int h = 0; h < 8; h++) {
        S[h * 512 + t]       = acc0[h] + seb[(long)h * 262144 + t];
        S[h * 512 + t + 256] = acc1[h] + seb[(long)h * 262144 + t + 256];
    }
    __syncthreads();

    const int w = t >> 5, l = t & 31;
    float* Sr = S + w * 512;
    float4 v[4];
    float mx = -3.0e38f;
#pragma unroll
    for (int k2 = 0; k2 < 4; k2++) {
        v[k2] = *(const float4*)(Sr + k2 * 128 + l * 4);
        mx = fmaxf(mx, fmaxf(fmaxf(v[k2].x, v[k2].y), fmaxf(v[k2].z, v[k2].w)));
    }
#pragma unroll
    for (int off = 16; off > 0; off >>= 1)
        mx = fmaxf(mx, __shfl_xor_sync(0xFFFFFFFFu, mx, off));

    float sum = 0.f;
#pragma unroll
    for (int k2 = 0; k2 < 4; k2++) {
        v[k2].x = __expf(v[k2].x - mx);
        v[k2].y = __expf(v[k2].y - mx);
        v[k2].z = __expf(v[k2].z - mx);
        v[k2].w = __expf(v[k2].w - mx);
        sum += v[k2].x + v[k2].y + v[k2].z + v[k2].w;
    }
#pragma unroll
    for (int off = 16; off > 0; off >>= 1)
        sum += __shfl_xor_sync(0xFFFFFFFFu, sum, off);

    const float inv = 1.0f / sum;
    float* ab = attn + (long)(b * 8 + w) * 262144 + (long)n * 512;
#pragma unroll
    for (int k2 = 0; k2 < 4; k2++) {
        v[k2].x *= inv; v[k2].y *= inv; v[k2].z *= inv; v[k2].w *= inv;
        *(float4*)(ab + k2 * 128 + l * 4) = v[k2];
    }
}

extern "C" void kernel_launch(void* const* d_in, const int* in_sizes, int n_in,
                              void* d_out, int out_size)
{
    const float* iq    = (const float*)d_in[0];
    const float* ik    = (const float*)d_in[1];
    const float* iv    = (const float*)d_in[2];
    const float* embed = (const float*)d_in[3];
    const float* Wq    = (const float*)d_in[4];
    const float* Wk    = (const float*)d_in[5];
    const float* Wv    = (const float*)d_in[6];
    const float* Wp    = (const float*)d_in[7];
    const float* Wout  = (const float*)d_in[8];
    const float* bout  = (const float*)d_in[9];
    float* out = (float*)d_out;

    float *q, *k, *v, *wq, *se, *attn, *hid;
    cudaGetSymbolAddress((void**)&q,    g_q);
    cudaGetSymbolAddress((void**)&k,    g_k);
    cudaGetSymbolAddress((void**)&v,    g_v);
    cudaGetSymbolAddress((void**)&wq,   g_wq);
    cudaGetSymbolAddress((void**)&se,   g_se);
    cudaGetSymbolAddress((void**)&attn, g_attn);
    cudaGetSymbolAddress((void**)&hid,  g_hid);

    cudaFuncSetAttribute(k_fused_score_softmax,
                         cudaFuncAttributeMaxDynamicSharedMemorySize,
                         FK_SMEM_BYTES);

    // 1. q/k/v projections (q scaled)
    k_gemm_qkv<<<dim3(16, 4, 3), 256>>>(iq, ik, iv, Wq, Wk, Wv, q, k, v);

    // 2. wq[h] = Q_h @ Wp_h^T  (z = h, K = 32)
    k_gemm_nt<<<dim3(16, 4, 8), 256>>>(
        q, 256, 0, 32,
        Wp, 256, 0, 32,
        wq, 256, 0, 262144,
        256, 32, 1.0f);

    // 3. scores_e[b*8+h] = Q_h @ K_h^T  (z = b*8+h, K = 32)
    k_gemm_nt<<<dim3(8, 8, 16), 256>>>(
        q, 256, 131072, 32,
        k, 256, 131072, 32,
        se, 512, 2097152, 262144,
        512, 32, 1.0f);

    // 4. fused scores_p + softmax -> attn
    k_fused_score_softmax<<<dim3(512, 2), 256, FK_SMEM_BYTES>>>(embed, wq, se, attn);

    // 5. hidden = attn @ V_h  (z = b*8+h, N = 32, K = 512)
    k_gemm_nn32<<<dim3(8, 1, 16), 256>>>(
        attn, 512, 2097152, 262144,
        v, 256, 131072, 32,
        hid, 256, 131072, 32,
        32, 512, 1.0f);

    // 6. out = hidden @ Wout + bout
    k_gemm_nn64<<<dim3(16, 4, 1), 256>>>(
        hid, 256, 0, 0,
        Wout, 256, 0, 0,
        out, 256, 0, 0,
        256, 256, 1.0f, bout);
}